// round 10
// baseline (speedup 1.0000x reference)
#include <cuda_runtime.h>

// ============================================================================
// GeneratorQuantumCircuit: 4-qubit state-vector simulation, 1 thread = 1 batch
// element. State = 16 complex amplitudes packed as (re,im) f32x2 in 64-bit
// registers. RX layer built as a product state; CNOTs are register renames;
// RY gates use packed fma.rn.f32x2 (re and im see the same real map).
// Weight cos/sin are batch-uniform -> precomputed by an 8-thread pre-kernel.
// ============================================================================

typedef unsigned long long u64;

__device__ float g_wc[8];   // cos(weights[l][w] * 0.5)
__device__ float g_ws[8];   // sin(weights[l][w] * 0.5)

__global__ void prep_weights_kernel(const float* __restrict__ w) {
    int i = threadIdx.x;
    if (i < 8) {
        float th = 0.5f * w[i];
        g_wc[i] = cosf(th);   // accurate versions: only 8 threads, cost-free
        g_ws[i] = sinf(th);
    }
}

// ---- packed f32x2 helpers (Blackwell sm_100+) ------------------------------

__device__ __forceinline__ u64 pk2(float lo, float hi) {
    u64 r; asm("mov.b64 %0, {%1, %2};" : "=l"(r) : "f"(lo), "f"(hi)); return r;
}
__device__ __forceinline__ void unpk2(u64 v, float& lo, float& hi) {
    asm("mov.b64 {%0, %1}, %2;" : "=f"(lo), "=f"(hi) : "l"(v));
}
__device__ __forceinline__ u64 mul2(u64 a, u64 b) {
    u64 r; asm("mul.rn.f32x2 %0, %1, %2;" : "=l"(r) : "l"(a), "l"(b)); return r;
}
__device__ __forceinline__ u64 fma2(u64 a, u64 b, u64 c) {
    u64 r; asm("fma.rn.f32x2 %0, %1, %2, %3;" : "=l"(r) : "l"(a), "l"(b), "l"(c)); return r;
}

// CNOT(ctrl C, tgt T): for ctrl bit = 1, swap target 0<->1. Pure register
// permutation once fully unrolled -> zero SASS instructions.
template <int C, int T>
__device__ __forceinline__ void cnot(u64* a) {
#pragma unroll
    for (int i = 0; i < 16; i++) {
        if ((i & (1 << C)) && !(i & (1 << T))) {
            u64 t = a[i];
            a[i] = a[i | (1 << T)];
            a[i | (1 << T)] = t;
        }
    }
}

__global__ void __launch_bounds__(256)
qc_kernel(const float4* __restrict__ noise, float4* __restrict__ out, int n) {
    int b = blockIdx.x * blockDim.x + threadIdx.x;
    if (b >= n) return;

    // ---- load noise angles, compute RX cos/sin -----------------------------
    float4 nz = noise[b];
    float c[4], s[4];
    __sincosf(0.5f * nz.x, &s[0], &c[0]);
    __sincosf(0.5f * nz.y, &s[1], &c[1]);
    __sincosf(0.5f * nz.z, &s[2], &c[2]);
    __sincosf(0.5f * nz.w, &s[3], &c[3]);

    // ---- build product state: amp(i) = prod_w (i_w ? -i*s_w : c_w) ---------
    // a[i] packed (re, im). Multiplying (re,im) by (0,-s) -> (im*s, -re*s):
    // implemented as mul2( pk2(im,re), pk2(s,-s) ).
    u64 a[16];
    a[0] = pk2(1.0f, 0.0f);
#pragma unroll
    for (int w = 0; w < 4; w++) {
        const int h = 1 << w;
        u64 sn = pk2(s[w], -s[w]);
        u64 cc = pk2(c[w], c[w]);
#pragma unroll
        for (int i = 0; i < (1 << w); i++) {
            float re, im;
            unpk2(a[i], re, im);
            a[i + h] = mul2(pk2(im, re), sn);  // a[i] * (-i s)
            a[i]     = mul2(a[i], cc);         // a[i] * c
        }
    }

    // ---- 2 layers: CNOT ring + RY(weights) ---------------------------------
#pragma unroll
    for (int layer = 0; layer < 2; layer++) {
        cnot<0, 1>(a);
        cnot<1, 2>(a);
        cnot<2, 3>(a);
        cnot<3, 0>(a);

#pragma unroll
        for (int w = 0; w < 4; w++) {
            float cw = g_wc[layer * 4 + w];
            float sw = g_ws[layer * 4 + w];
            u64 cc = pk2(cw, cw);
            u64 ss = pk2(sw, sw);
            u64 ns = pk2(-sw, -sw);
            const int h = 1 << w;
#pragma unroll
            for (int i = 0; i < 16; i++) {
                if (i & h) continue;
                u64 a0 = a[i], a1 = a[i | h];
                // new0 = c*a0 - s*a1 ; new1 = s*a0 + c*a1  (same map on re & im)
                a[i]     = fma2(ns, a1, mul2(cc, a0));
                a[i | h] = fma2(cc, a1, mul2(ss, a0));
            }
        }
    }

    // ---- probabilities + per-wire marginals (p0 of each qubit) -------------
    float p[16];
#pragma unroll
    for (int i = 0; i < 16; i++) {
        float re, im;
        unpk2(a[i], re, im);
        p[i] = fmaf(re, re, im * im);
    }

    // out[w] = sum of p[i] over indices with bit w == 0
    // share pairwise partial sums where easy; compiler CSEs the rest
    float4 o;
    o.x = ((p[0] + p[2]) + (p[4] + p[6])) + ((p[8] + p[10]) + (p[12] + p[14]));
    o.y = ((p[0] + p[1]) + (p[4] + p[5])) + ((p[8] + p[9])  + (p[12] + p[13]));
    o.z = ((p[0] + p[1]) + (p[2] + p[3])) + ((p[8] + p[9])  + (p[10] + p[11]));
    o.w = ((p[0] + p[1]) + (p[2] + p[3])) + ((p[4] + p[5])  + (p[6]  + p[7]));

    out[b] = o;
}

extern "C" void kernel_launch(void* const* d_in, const int* in_sizes, int n_in,
                              void* d_out, int out_size) {
    const float* noise   = (const float*)d_in[0];   // (B, 4) f32
    const float* weights = (const float*)d_in[1];   // (2, 4) f32
    int B = in_sizes[0] / 4;

    prep_weights_kernel<<<1, 32>>>(weights);

    int threads = 256;
    int blocks = (B + threads - 1) / threads;
    qc_kernel<<<blocks, threads>>>((const float4*)noise, (float4*)d_out, B);
}